// round 3
// baseline (speedup 1.0000x reference)
#include <cuda_runtime.h>
#include <cuda_bf16.h>

// 2-layer GCN via CSC build + gather aggregation (no FP atomics in hot path).
// NOTE: edge_index is int32 (JAX x64 disabled => jnp.int64 silently -> int32).
//
// deg[c] = 1 + sum_{e: col=c} w[e];  dinv = rsqrt(deg)
// layer1: agg[c] = dinv[c] * sum_in (dinv[r]*w) * h[r]  +  h[c]*dinv[c]^2
//         s[c]   = relu(agg[c] + b1) . W2          (layer-2 projection fused)
// layer2: out[c] = dinv[c] * sum_in (dinv[r]*w) * s[r] + s[c]*dinv[c]^2 + b2

#define N_NODES 100000
#define N_EDGES 1600000
#define C 64
#define SCAN_B 256
#define NB ((N_NODES + SCAN_B - 1) / SCAN_B)   // 391

__device__ int   g_cnt[N_NODES];
__device__ float g_deg[N_NODES];
__device__ float g_dinv[N_NODES];
__device__ int   g_off[N_NODES + 1];
__device__ int   g_cursor[N_NODES];
__device__ int   g_bsum[NB];
__device__ int   g_bsum_sc[NB];
__device__ __align__(16) uint2 g_edge[N_EDGES];           // {src, coef bits}
__device__ __align__(16) float g_h[(size_t)N_NODES * C];
__device__ float g_s[N_NODES];

__global__ void k_init() {
    int i = blockIdx.x * blockDim.x + threadIdx.x;
    if (i < N_NODES) { g_cnt[i] = 0; g_deg[i] = 1.0f; }   // self-loop weight
}

__global__ void k_edge_count(const int* __restrict__ ei,
                             const float* __restrict__ w) {
    int e = blockIdx.x * blockDim.x + threadIdx.x;
    if (e >= N_EDGES) return;
    int c = ei[N_EDGES + e];
    atomicAdd(&g_cnt[c], 1);
    atomicAdd(&g_deg[c], w[e]);
}

__global__ void k_dinv() {
    int i = blockIdx.x * blockDim.x + threadIdx.x;
    if (i >= N_NODES) return;
    float d = g_deg[i];
    g_dinv[i] = (d > 0.0f) ? rsqrtf(d) : 0.0f;
}

// ---- exclusive scan over g_cnt (3 kernels) ----
__global__ void k_scanA() {
    __shared__ int sh[SCAN_B];
    int t = threadIdx.x;
    int i = blockIdx.x * SCAN_B + t;
    int v = (i < N_NODES) ? g_cnt[i] : 0;
    sh[t] = v;
    __syncthreads();
#pragma unroll
    for (int off = 1; off < SCAN_B; off <<= 1) {
        int x = (t >= off) ? sh[t - off] : 0;
        __syncthreads();
        sh[t] += x;
        __syncthreads();
    }
    if (i < N_NODES) g_off[i] = sh[t] - v;     // exclusive within block
    if (t == SCAN_B - 1) g_bsum[blockIdx.x] = sh[t];
}

__global__ void k_scanB() {
    __shared__ int sh[512];
    int t = threadIdx.x;
    sh[t] = (t < NB) ? g_bsum[t] : 0;
    __syncthreads();
#pragma unroll
    for (int off = 1; off < 512; off <<= 1) {
        int x = (t >= off) ? sh[t - off] : 0;
        __syncthreads();
        sh[t] += x;
        __syncthreads();
    }
    if (t < NB) g_bsum_sc[t] = sh[t] - g_bsum[t];  // exclusive
}

__global__ void k_scanC() {
    int i = blockIdx.x * blockDim.x + threadIdx.x;
    if (i >= N_NODES) return;
    int o = g_off[i] + g_bsum_sc[blockIdx.x];
    g_off[i] = o;
    g_cursor[i] = o;
    if (i == 0) g_off[N_NODES] = N_EDGES;
}

__global__ void k_fill(const int* __restrict__ ei,
                       const float* __restrict__ w) {
    int e = blockIdx.x * blockDim.x + threadIdx.x;
    if (e >= N_EDGES) return;
    int r = ei[e];
    int c = ei[N_EDGES + e];
    float coef = g_dinv[r] * w[e];
    int pos = atomicAdd(&g_cursor[c], 1);
    g_edge[pos] = make_uint2((unsigned)r, __float_as_uint(coef));
}

// h = x @ W1 : 256 threads = 4 nodes x 64 channels, W1 in smem
__global__ void k_gemm1(const float* __restrict__ x,
                        const float* __restrict__ W1) {
    __shared__ float Ws[64 * 64];
    __shared__ float xs[4 * 64];
    int t = threadIdx.x;
#pragma unroll
    for (int i = 0; i < 16; i++) Ws[t + i * 256] = W1[t + i * 256];

    int nodeBase = blockIdx.x * 4;
    int nl = t >> 6;
    int j = t & 63;
    xs[t] = x[(size_t)nodeBase * C + t];
    __syncthreads();

    float acc = 0.0f;
#pragma unroll
    for (int k = 0; k < 64; k++)
        acc = fmaf(xs[nl * 64 + k], Ws[k * 64 + j], acc);
    g_h[(size_t)(nodeBase + nl) * C + j] = acc;
}

// fused layer1 aggregate + relu + layer2 projection. one warp per node.
// lane handles channels (2*lane, 2*lane+1).
__global__ void k_layer1(const float* __restrict__ b1,
                         const float* __restrict__ W2) {
    int warp = (blockIdx.x * blockDim.x + threadIdx.x) >> 5;
    int lane = threadIdx.x & 31;
    if (warp >= N_NODES) return;
    int n = warp;

    int begin = g_off[n];
    int end   = g_off[n + 1];

    float a0 = 0.0f, a1 = 0.0f;
    for (int base = begin; base < end; base += 32) {
        int idx = base + lane;
        uint2 em = (idx < end) ? g_edge[idx] : make_uint2(0u, 0u);
        int m = min(32, end - base);
        for (int j = 0; j < m; j++) {
            int   r  = __shfl_sync(0xffffffffu, (int)em.x, j);
            float cf = __shfl_sync(0xffffffffu, __uint_as_float(em.y), j);
            float2 hv = *reinterpret_cast<const float2*>(g_h + (size_t)r * C + lane * 2);
            a0 = fmaf(cf, hv.x, a0);
            a1 = fmaf(cf, hv.y, a1);
        }
    }

    float din = g_dinv[n];
    float2 hn = *reinterpret_cast<const float2*>(g_h + (size_t)n * C + lane * 2);
    float v0 = fmaxf(a0 * din + hn.x * din * din + b1[lane * 2],     0.0f);
    float v1 = fmaxf(a1 * din + hn.y * din * din + b1[lane * 2 + 1], 0.0f);
    float s = v0 * W2[lane * 2] + v1 * W2[lane * 2 + 1];
#pragma unroll
    for (int off = 16; off > 0; off >>= 1)
        s += __shfl_xor_sync(0xffffffffu, s, off);
    if (lane == 0) g_s[n] = s;
}

// layer2 gather: one warp per node, lanes parallel over edges.
__global__ void k_layer2(const float* __restrict__ b2,
                         float* __restrict__ out) {
    int warp = (blockIdx.x * blockDim.x + threadIdx.x) >> 5;
    int lane = threadIdx.x & 31;
    if (warp >= N_NODES) return;
    int n = warp;

    int begin = g_off[n];
    int end   = g_off[n + 1];

    float acc = 0.0f;
    for (int idx = begin + lane; idx < end; idx += 32) {
        uint2 em = g_edge[idx];
        acc = fmaf(__uint_as_float(em.y), g_s[em.x], acc);
    }
#pragma unroll
    for (int off = 16; off > 0; off >>= 1)
        acc += __shfl_xor_sync(0xffffffffu, acc, off);

    if (lane == 0) {
        float din = g_dinv[n];
        out[n] = acc * din + g_s[n] * din * din + b2[0];
    }
}

extern "C" void kernel_launch(void* const* d_in, const int* in_sizes, int n_in,
                              void* d_out, int out_size) {
    const float* x  = (const float*)d_in[0];
    const int*   ei = (const int*)d_in[1];
    const float* w  = (const float*)d_in[2];
    const float* W1 = (const float*)d_in[3];
    const float* b1 = (const float*)d_in[4];
    const float* W2 = (const float*)d_in[5];
    const float* b2 = (const float*)d_in[6];
    float* out = (float*)d_out;

    const int T = 256;
    k_init<<<NB, T>>>();
    k_edge_count<<<(N_EDGES + T - 1) / T, T>>>(ei, w);
    k_dinv<<<NB, T>>>();
    k_scanA<<<NB, SCAN_B>>>();
    k_scanB<<<1, 512>>>();
    k_scanC<<<NB, SCAN_B>>>();
    k_fill<<<(N_EDGES + T - 1) / T, T>>>(ei, w);
    k_gemm1<<<N_NODES / 4, T>>>(x, W1);
    k_layer1<<<(N_NODES * 32 + T - 1) / T, T>>>(b1, W2);
    k_layer2<<<(N_NODES * 32 + T - 1) / T, T>>>(b2, out);
}

// round 4
// speedup vs baseline: 1.0324x; 1.0324x over previous
#include <cuda_runtime.h>
#include <cuda_bf16.h>

// 2-layer GCN via CSC build + gather aggregation (no FP atomics anywhere).
// edge_index arrives as int32 (JAX x64 disabled).
//
// deg[c] = 1 + sum_{e: col=c} w[e];  dinv = rsqrt(deg)
// layer1: agg[c] = dinv[c] * sum_in (dinv[r]*w) * h[r]  +  h[c]*dinv[c]^2
//         s[c]   = relu(agg[c] + b1) . W2          (layer-2 projection fused)
// layer2: out[c] = dinv[c] * sum_in (dinv[r]*w) * s[r] + s[c]*dinv[c]^2 + b2

#define N_NODES 100000
#define N_EDGES 1600000
#define C 64
#define SCAN_B 256
#define NB ((N_NODES + SCAN_B - 1) / SCAN_B)   // 391
#define W_SCALE 67108864.0f                    // 2^26 fixed-point for w
#define W_MASK  ((1ULL << 40) - 1ULL)

__device__ unsigned long long g_pack[N_NODES];   // {cnt:24 | sum_w fixed:40}
__device__ int   g_cnt[N_NODES];
__device__ float g_dinv[N_NODES];
__device__ int   g_off[N_NODES + 1];
__device__ int   g_cursor[N_NODES];
__device__ int   g_bsum[NB];
__device__ int   g_bsum_sc[NB];
__device__ __align__(16) uint2 g_edge[N_EDGES];           // {src, coef bits}
__device__ __align__(16) float g_h[(size_t)N_NODES * C];
__device__ float g_s[N_NODES];

__global__ void k_init() {
    int i = blockIdx.x * blockDim.x + threadIdx.x;
    if (i < N_NODES) g_pack[i] = 0ULL;
}

// one packed u64 atomic per edge: count in high bits, fixed-point w in low
__global__ void k_edge_count(const int* __restrict__ ei,
                             const float* __restrict__ w) {
    int t = blockIdx.x * blockDim.x + threadIdx.x;
    if (t * 2 >= N_EDGES) return;
    int2   cc = *reinterpret_cast<const int2*>(ei + N_EDGES + t * 2);
    float2 ww = *reinterpret_cast<const float2*>(w + t * 2);
    unsigned long long p0 = (1ULL << 40) + (unsigned long long)(ww.x * W_SCALE);
    unsigned long long p1 = (1ULL << 40) + (unsigned long long)(ww.y * W_SCALE);
    atomicAdd(&g_pack[cc.x], p0);
    atomicAdd(&g_pack[cc.y], p1);
}

__global__ void k_dinv() {
    int i = blockIdx.x * blockDim.x + threadIdx.x;
    if (i >= N_NODES) return;
    unsigned long long p = g_pack[i];
    g_cnt[i] = (int)(p >> 40);
    float deg = 1.0f + (float)(p & W_MASK) * (1.0f / W_SCALE);
    g_dinv[i] = rsqrtf(deg);   // deg >= 1 always (self-loop)
}

// ---- exclusive scan over g_cnt (3 kernels) ----
__global__ void k_scanA() {
    __shared__ int sh[SCAN_B];
    int t = threadIdx.x;
    int i = blockIdx.x * SCAN_B + t;
    int v = (i < N_NODES) ? g_cnt[i] : 0;
    sh[t] = v;
    __syncthreads();
#pragma unroll
    for (int off = 1; off < SCAN_B; off <<= 1) {
        int x = (t >= off) ? sh[t - off] : 0;
        __syncthreads();
        sh[t] += x;
        __syncthreads();
    }
    if (i < N_NODES) g_off[i] = sh[t] - v;     // exclusive within block
    if (t == SCAN_B - 1) g_bsum[blockIdx.x] = sh[t];
}

__global__ void k_scanB() {
    __shared__ int sh[512];
    int t = threadIdx.x;
    sh[t] = (t < NB) ? g_bsum[t] : 0;
    __syncthreads();
#pragma unroll
    for (int off = 1; off < 512; off <<= 1) {
        int x = (t >= off) ? sh[t - off] : 0;
        __syncthreads();
        sh[t] += x;
        __syncthreads();
    }
    if (t < NB) g_bsum_sc[t] = sh[t] - g_bsum[t];  // exclusive
}

__global__ void k_scanC() {
    int i = blockIdx.x * blockDim.x + threadIdx.x;
    if (i >= N_NODES) return;
    int o = g_off[i] + g_bsum_sc[blockIdx.x];
    g_off[i] = o;
    g_cursor[i] = o;
    if (i == 0) g_off[N_NODES] = N_EDGES;
}

__global__ void k_fill(const int* __restrict__ ei,
                       const float* __restrict__ w) {
    int e = blockIdx.x * blockDim.x + threadIdx.x;
    if (e >= N_EDGES) return;
    int r = ei[e];
    int c = ei[N_EDGES + e];
    float coef = g_dinv[r] * w[e];
    int pos = atomicAdd(&g_cursor[c], 1);
    g_edge[pos] = make_uint2((unsigned)r, __float_as_uint(coef));
}

// h = x @ W1 : 256 threads = 4 nodes x 64 channels, W1 in smem
__global__ void k_gemm1(const float* __restrict__ x,
                        const float* __restrict__ W1) {
    __shared__ float Ws[64 * 64];
    __shared__ float xs[4 * 64];
    int t = threadIdx.x;
#pragma unroll
    for (int i = 0; i < 16; i++) Ws[t + i * 256] = W1[t + i * 256];

    int nodeBase = blockIdx.x * 4;
    int nl = t >> 6;
    int j = t & 63;
    xs[t] = x[(size_t)nodeBase * C + t];
    __syncthreads();

    float acc = 0.0f;
#pragma unroll
    for (int k = 0; k < 64; k++)
        acc = fmaf(xs[nl * 64 + k], Ws[k * 64 + j], acc);
    g_h[(size_t)(nodeBase + nl) * C + j] = acc;
}

// fused layer1 aggregate + relu + layer2 projection. one warp per node.
// lane owns channels (2*lane, 2*lane+1). edges processed 4-deep for MLP;
// edge records are broadcast loads (all lanes same address).
__global__ void k_layer1(const float* __restrict__ b1,
                         const float* __restrict__ W2) {
    int n = (blockIdx.x * blockDim.x + threadIdx.x) >> 5;
    int lane = threadIdx.x & 31;
    if (n >= N_NODES) return;

    int idx = g_off[n];
    int end = g_off[n + 1];
    const float2* __restrict__ hp = reinterpret_cast<const float2*>(g_h);

    float a0 = 0.0f, a1 = 0.0f;
    for (; idx + 4 <= end; idx += 4) {
        uint2 e0 = g_edge[idx + 0];
        uint2 e1 = g_edge[idx + 1];
        uint2 e2 = g_edge[idx + 2];
        uint2 e3 = g_edge[idx + 3];
        float2 h0 = hp[e0.x * 32u + lane];
        float2 h1 = hp[e1.x * 32u + lane];
        float2 h2 = hp[e2.x * 32u + lane];
        float2 h3 = hp[e3.x * 32u + lane];
        float c0 = __uint_as_float(e0.y), c1 = __uint_as_float(e1.y);
        float c2 = __uint_as_float(e2.y), c3 = __uint_as_float(e3.y);
        a0 = fmaf(c0, h0.x, a0); a1 = fmaf(c0, h0.y, a1);
        a0 = fmaf(c1, h1.x, a0); a1 = fmaf(c1, h1.y, a1);
        a0 = fmaf(c2, h2.x, a0); a1 = fmaf(c2, h2.y, a1);
        a0 = fmaf(c3, h3.x, a0); a1 = fmaf(c3, h3.y, a1);
    }
    for (; idx < end; idx++) {
        uint2 e = g_edge[idx];
        float2 hv = hp[e.x * 32u + lane];
        float cf = __uint_as_float(e.y);
        a0 = fmaf(cf, hv.x, a0);
        a1 = fmaf(cf, hv.y, a1);
    }

    float din = g_dinv[n];
    float2 hn = hp[(unsigned)n * 32u + lane];
    float v0 = fmaxf(fmaf(a0, din, hn.x * din * din) + b1[lane * 2],     0.0f);
    float v1 = fmaxf(fmaf(a1, din, hn.y * din * din) + b1[lane * 2 + 1], 0.0f);
    float s = v0 * W2[lane * 2] + v1 * W2[lane * 2 + 1];
#pragma unroll
    for (int off = 16; off > 0; off >>= 1)
        s += __shfl_xor_sync(0xffffffffu, s, off);
    if (lane == 0) g_s[n] = s;
}

// layer2 gather: one warp per node, lanes parallel over edges.
__global__ void k_layer2(const float* __restrict__ b2,
                         float* __restrict__ out) {
    int n = (blockIdx.x * blockDim.x + threadIdx.x) >> 5;
    int lane = threadIdx.x & 31;
    if (n >= N_NODES) return;

    int begin = g_off[n];
    int end   = g_off[n + 1];

    float acc = 0.0f;
    for (int idx = begin + lane; idx < end; idx += 32) {
        uint2 em = g_edge[idx];
        acc = fmaf(__uint_as_float(em.y), g_s[em.x], acc);
    }
#pragma unroll
    for (int off = 16; off > 0; off >>= 1)
        acc += __shfl_xor_sync(0xffffffffu, acc, off);

    if (lane == 0) {
        float din = g_dinv[n];
        out[n] = fmaf(acc, din, g_s[n] * din * din) + b2[0];
    }
}

extern "C" void kernel_launch(void* const* d_in, const int* in_sizes, int n_in,
                              void* d_out, int out_size) {
    const float* x  = (const float*)d_in[0];
    const int*   ei = (const int*)d_in[1];
    const float* w  = (const float*)d_in[2];
    const float* W1 = (const float*)d_in[3];
    const float* b1 = (const float*)d_in[4];
    const float* W2 = (const float*)d_in[5];
    const float* b2 = (const float*)d_in[6];
    float* out = (float*)d_out;

    const int T = 256;
    k_init<<<NB, T>>>();
    k_edge_count<<<(N_EDGES / 2 + T - 1) / T, T>>>(ei, w);
    k_dinv<<<NB, T>>>();
    k_scanA<<<NB, SCAN_B>>>();
    k_scanB<<<1, 512>>>();
    k_scanC<<<NB, SCAN_B>>>();
    k_fill<<<(N_EDGES + T - 1) / T, T>>>(ei, w);
    k_gemm1<<<N_NODES / 4, T>>>(x, W1);
    k_layer1<<<(N_NODES * 32 + T - 1) / T, T>>>(b1, W2);
    k_layer2<<<(N_NODES * 32 + T - 1) / T, T>>>(b2, out);
}

// round 5
// speedup vs baseline: 1.5642x; 1.5152x over previous
#include <cuda_runtime.h>
#include <cuda_bf16.h>

// 2-layer GCN via CSC build + gather aggregation (no FP atomics anywhere).
// edge_index arrives as int32 (JAX x64 disabled).

#define N_NODES 100000
#define N_EDGES 1600000
#define C 64
#define SCAN_B 256
#define NB ((N_NODES + SCAN_B - 1) / SCAN_B)   // 391
#define W_SCALE 67108864.0f                    // 2^26 fixed-point for w
#define W_MASK  ((1ULL << 40) - 1ULL)
#define GB 64                                   // gemm nodes per block
#define GEMM_GRID ((N_NODES + GB - 1) / GB)    // 1563

__device__ unsigned long long g_pack[N_NODES];   // {cnt:24 | sum_w fixed:40}
__device__ int   g_cnt[N_NODES];
__device__ float g_dinv[N_NODES];
__device__ int   g_off[N_NODES + 1];
__device__ int   g_cursor[N_NODES];
__device__ int   g_bsum[NB];
__device__ int   g_bsum_sc[NB];
__device__ __align__(16) uint2 g_edge[N_EDGES];           // {src, coef bits}
__device__ __align__(16) float g_h[(size_t)N_NODES * C];
__device__ float g_s[N_NODES];

// h = x @ W1, register-tiled: 64 nodes x 64 ch per block, 4x4 per thread.
// Also zeroes g_pack (grid*256 = 400k threads >= N_NODES).
__global__ void k_gemm1(const float* __restrict__ x,
                        const float* __restrict__ W1) {
    __shared__ float xs[GB][72];     // [node][k], stride 72 floats (16B-mult, +8 bank skew)
    __shared__ float Ws[64][64];     // [k][ch]
    int t = threadIdx.x;
    int nb = blockIdx.x * GB;

    int gi = blockIdx.x * 256 + t;
    if (gi < N_NODES) g_pack[gi] = 0ULL;

#pragma unroll
    for (int i = 0; i < 16; i++)
        ((float*)Ws)[t + i * 256] = W1[t + i * 256];

    {
        int nd = t >> 2;            // 0..63
        int q  = (t & 3) * 16;      // 0,16,32,48
        int node = nb + nd;
        if (node < N_NODES) {
            const float* xp = x + (size_t)node * 64 + q;
            float4 v0 = *(const float4*)(xp);
            float4 v1 = *(const float4*)(xp + 4);
            float4 v2 = *(const float4*)(xp + 8);
            float4 v3 = *(const float4*)(xp + 12);
            *(float4*)&xs[nd][q]      = v0;
            *(float4*)&xs[nd][q + 4]  = v1;
            *(float4*)&xs[nd][q + 8]  = v2;
            *(float4*)&xs[nd][q + 12] = v3;
        }
    }
    __syncthreads();

    int ch4 = (t & 15) * 4;         // channel group
    int nd0 = (t >> 4) * 4;         // node group

    float acc[4][4];
#pragma unroll
    for (int i = 0; i < 4; i++)
#pragma unroll
        for (int j = 0; j < 4; j++) acc[i][j] = 0.0f;

#pragma unroll 4
    for (int k = 0; k < 64; k++) {
        float4 wv = *(const float4*)&Ws[k][ch4];
        float x0 = xs[nd0 + 0][k];
        float x1 = xs[nd0 + 1][k];
        float x2 = xs[nd0 + 2][k];
        float x3 = xs[nd0 + 3][k];
        acc[0][0] = fmaf(x0, wv.x, acc[0][0]); acc[0][1] = fmaf(x0, wv.y, acc[0][1]);
        acc[0][2] = fmaf(x0, wv.z, acc[0][2]); acc[0][3] = fmaf(x0, wv.w, acc[0][3]);
        acc[1][0] = fmaf(x1, wv.x, acc[1][0]); acc[1][1] = fmaf(x1, wv.y, acc[1][1]);
        acc[1][2] = fmaf(x1, wv.z, acc[1][2]); acc[1][3] = fmaf(x1, wv.w, acc[1][3]);
        acc[2][0] = fmaf(x2, wv.x, acc[2][0]); acc[2][1] = fmaf(x2, wv.y, acc[2][1]);
        acc[2][2] = fmaf(x2, wv.z, acc[2][2]); acc[2][3] = fmaf(x2, wv.w, acc[2][3]);
        acc[3][0] = fmaf(x3, wv.x, acc[3][0]); acc[3][1] = fmaf(x3, wv.y, acc[3][1]);
        acc[3][2] = fmaf(x3, wv.z, acc[3][2]); acc[3][3] = fmaf(x3, wv.w, acc[3][3]);
    }

#pragma unroll
    for (int i = 0; i < 4; i++) {
        int node = nb + nd0 + i;
        if (node < N_NODES) {
            float4 o = make_float4(acc[i][0], acc[i][1], acc[i][2], acc[i][3]);
            *(float4*)(g_h + (size_t)node * 64 + ch4) = o;
        }
    }
}

// one packed u64 atomic per edge: count in high bits, fixed-point w in low
__global__ void k_edge_count(const int* __restrict__ ei,
                             const float* __restrict__ w) {
    int t = blockIdx.x * blockDim.x + threadIdx.x;
    if (t * 2 >= N_EDGES) return;
    int2   cc = *reinterpret_cast<const int2*>(ei + N_EDGES + t * 2);
    float2 ww = *reinterpret_cast<const float2*>(w + t * 2);
    unsigned long long p0 = (1ULL << 40) + (unsigned long long)(ww.x * W_SCALE);
    unsigned long long p1 = (1ULL << 40) + (unsigned long long)(ww.y * W_SCALE);
    atomicAdd(&g_pack[cc.x], p0);
    atomicAdd(&g_pack[cc.y], p1);
}

__global__ void k_dinv() {
    int i = blockIdx.x * blockDim.x + threadIdx.x;
    if (i >= N_NODES) return;
    unsigned long long p = g_pack[i];
    g_cnt[i] = (int)(p >> 40);
    float deg = 1.0f + (float)(p & W_MASK) * (1.0f / W_SCALE);
    g_dinv[i] = rsqrtf(deg);
}

// ---- exclusive scan over g_cnt (3 kernels) ----
__global__ void k_scanA() {
    __shared__ int sh[SCAN_B];
    int t = threadIdx.x;
    int i = blockIdx.x * SCAN_B + t;
    int v = (i < N_NODES) ? g_cnt[i] : 0;
    sh[t] = v;
    __syncthreads();
#pragma unroll
    for (int off = 1; off < SCAN_B; off <<= 1) {
        int x = (t >= off) ? sh[t - off] : 0;
        __syncthreads();
        sh[t] += x;
        __syncthreads();
    }
    if (i < N_NODES) g_off[i] = sh[t] - v;
    if (t == SCAN_B - 1) g_bsum[blockIdx.x] = sh[t];
}

__global__ void k_scanB() {
    __shared__ int sh[512];
    int t = threadIdx.x;
    sh[t] = (t < NB) ? g_bsum[t] : 0;
    __syncthreads();
#pragma unroll
    for (int off = 1; off < 512; off <<= 1) {
        int x = (t >= off) ? sh[t - off] : 0;
        __syncthreads();
        sh[t] += x;
        __syncthreads();
    }
    if (t < NB) g_bsum_sc[t] = sh[t] - g_bsum[t];
}

__global__ void k_scanC() {
    int i = blockIdx.x * blockDim.x + threadIdx.x;
    if (i >= N_NODES) return;
    int o = g_off[i] + g_bsum_sc[blockIdx.x];
    g_off[i] = o;
    g_cursor[i] = o;
    if (i == 0) g_off[N_NODES] = N_EDGES;
}

__global__ void k_fill(const int* __restrict__ ei,
                       const float* __restrict__ w) {
    int t = blockIdx.x * blockDim.x + threadIdx.x;
    if (t * 2 >= N_EDGES) return;
    int2   rr = *reinterpret_cast<const int2*>(ei + t * 2);
    int2   cc = *reinterpret_cast<const int2*>(ei + N_EDGES + t * 2);
    float2 ww = *reinterpret_cast<const float2*>(w + t * 2);
    float coef0 = g_dinv[rr.x] * ww.x;
    float coef1 = g_dinv[rr.y] * ww.y;
    int p0 = atomicAdd(&g_cursor[cc.x], 1);
    g_edge[p0] = make_uint2((unsigned)rr.x, __float_as_uint(coef0));
    int p1 = atomicAdd(&g_cursor[cc.y], 1);
    g_edge[p1] = make_uint2((unsigned)rr.y, __float_as_uint(coef1));
}

// fused layer1 aggregate + relu + layer2 projection. one warp per node.
__global__ void k_layer1(const float* __restrict__ b1,
                         const float* __restrict__ W2) {
    int n = (blockIdx.x * blockDim.x + threadIdx.x) >> 5;
    int lane = threadIdx.x & 31;
    if (n >= N_NODES) return;

    int idx = g_off[n];
    int end = g_off[n + 1];
    const float2* __restrict__ hp = reinterpret_cast<const float2*>(g_h);

    float a0 = 0.0f, a1 = 0.0f;
    for (; idx + 4 <= end; idx += 4) {
        uint2 e0 = g_edge[idx + 0];
        uint2 e1 = g_edge[idx + 1];
        uint2 e2 = g_edge[idx + 2];
        uint2 e3 = g_edge[idx + 3];
        float2 h0 = hp[e0.x * 32u + lane];
        float2 h1 = hp[e1.x * 32u + lane];
        float2 h2 = hp[e2.x * 32u + lane];
        float2 h3 = hp[e3.x * 32u + lane];
        float c0 = __uint_as_float(e0.y), c1 = __uint_as_float(e1.y);
        float c2 = __uint_as_float(e2.y), c3 = __uint_as_float(e3.y);
        a0 = fmaf(c0, h0.x, a0); a1 = fmaf(c0, h0.y, a1);
        a0 = fmaf(c1, h1.x, a0); a1 = fmaf(c1, h1.y, a1);
        a0 = fmaf(c2, h2.x, a0); a1 = fmaf(c2, h2.y, a1);
        a0 = fmaf(c3, h3.x, a0); a1 = fmaf(c3, h3.y, a1);
    }
    for (; idx < end; idx++) {
        uint2 e = g_edge[idx];
        float2 hv = hp[e.x * 32u + lane];
        float cf = __uint_as_float(e.y);
        a0 = fmaf(cf, hv.x, a0);
        a1 = fmaf(cf, hv.y, a1);
    }

    float din = g_dinv[n];
    float2 hn = hp[(unsigned)n * 32u + lane];
    float v0 = fmaxf(fmaf(a0, din, hn.x * din * din) + b1[lane * 2],     0.0f);
    float v1 = fmaxf(fmaf(a1, din, hn.y * din * din) + b1[lane * 2 + 1], 0.0f);
    float s = v0 * W2[lane * 2] + v1 * W2[lane * 2 + 1];
#pragma unroll
    for (int off = 16; off > 0; off >>= 1)
        s += __shfl_xor_sync(0xffffffffu, s, off);
    if (lane == 0) g_s[n] = s;
}

// layer2 gather: one warp per node, lanes parallel over edges.
__global__ void k_layer2(const float* __restrict__ b2,
                         float* __restrict__ out) {
    int n = (blockIdx.x * blockDim.x + threadIdx.x) >> 5;
    int lane = threadIdx.x & 31;
    if (n >= N_NODES) return;

    int begin = g_off[n];
    int end   = g_off[n + 1];

    float acc = 0.0f;
    for (int idx = begin + lane; idx < end; idx += 32) {
        uint2 em = g_edge[idx];
        acc = fmaf(__uint_as_float(em.y), g_s[em.x], acc);
    }
#pragma unroll
    for (int off = 16; off > 0; off >>= 1)
        acc += __shfl_xor_sync(0xffffffffu, acc, off);

    if (lane == 0) {
        float din = g_dinv[n];
        out[n] = fmaf(acc, din, g_s[n] * din * din) + b2[0];
    }
}

extern "C" void kernel_launch(void* const* d_in, const int* in_sizes, int n_in,
                              void* d_out, int out_size) {
    const float* x  = (const float*)d_in[0];
    const int*   ei = (const int*)d_in[1];
    const float* w  = (const float*)d_in[2];
    const float* W1 = (const float*)d_in[3];
    const float* b1 = (const float*)d_in[4];
    const float* W2 = (const float*)d_in[5];
    const float* b2 = (const float*)d_in[6];
    float* out = (float*)d_out;

    const int T = 256;
    k_gemm1<<<GEMM_GRID, T>>>(x, W1);                       // also zeros g_pack
    k_edge_count<<<(N_EDGES / 2 + T - 1) / T, T>>>(ei, w);
    k_dinv<<<NB, T>>>();
    k_scanA<<<NB, SCAN_B>>>();
    k_scanB<<<1, 512>>>();
    k_scanC<<<NB, SCAN_B>>>();
    k_fill<<<(N_EDGES / 2 + T - 1) / T, T>>>(ei, w);
    k_layer1<<<(N_NODES * 32 + T - 1) / T, T>>>(b1, W2);
    k_layer2<<<(N_NODES * 32 + T - 1) / T, T>>>(b2, out);
}